// round 8
// baseline (speedup 1.0000x reference)
#include <cuda_runtime.h>
#include <math.h>
#include <stdint.h>

// ---------------- problem constants ----------------
#define NNODES   100000
#define NEDGES   600000
#define NEDGES2  1500000
#define HID      128
#define HF4      32
#define NB       64
#define WT_LAYER 8192
#define SCAN_BS  1024

// ---------------- scratch (ping-pong feature buffers) ----------------------
__device__ float g_hA[(size_t)NNODES * HID];
__device__ float g_hB[(size_t)NNODES * HID];
__device__ float g_eA[(size_t)NEDGES * HID];
__device__ float g_eB[(size_t)NEDGES * HID];

struct ZB {
    int degN[2 * NNODES];         // [out | in]
    int degE[2 * NEDGES];
    int cnt [2 * NB];
    float pool[NB * 256];
};
__device__ ZB  g_zb;
__device__ int g_offN[NNODES];
__device__ int g_curN[NNODES];
__device__ int g_offE[NEDGES];
__device__ int g_curE[NEDGES];
__device__ int g_csrN[NEDGES];
__device__ int g_csrE[NEDGES2];
__device__ int g_bsum[SCAN_BS];
__device__ float g_Wt[6 * WT_LAYER * 2];

// ---------------- helpers ----------------
__device__ __forceinline__ void red_add_v2(float* addr, float x, float y) {
    asm volatile("red.global.add.v2.f32 [%0], {%1,%2};"
                 :: "l"(addr), "f"(x), "f"(y) : "memory");
}
__device__ __forceinline__ uint32_t f2tf32(float f) {
    uint32_t r;
    asm("cvt.rna.tf32.f32 %0, %1;" : "=r"(r) : "f"(f));
    return r;
}
__device__ __forceinline__ void mma_tf32(float& c0, float& c1, float& c2, float& c3,
                                         uint32_t a0, uint32_t a1, uint32_t a2, uint32_t a3,
                                         uint32_t b0, uint32_t b1) {
    asm volatile("mma.sync.aligned.m16n8k8.row.col.f32.tf32.tf32.f32 "
                 "{%0,%1,%2,%3}, {%4,%5,%6,%7}, {%8,%9}, {%0,%1,%2,%3};"
                 : "+f"(c0), "+f"(c1), "+f"(c2), "+f"(c3)
                 : "r"(a0), "r"(a1), "r"(a2), "r"(a3), "r"(b0), "r"(b1));
}
__device__ __forceinline__ float rsdeg_i(int d) {
    return rsqrtf(fmaxf((float)d, 1.f));
}

// ---------------- small kernels ----------------
__global__ void k_zero_all() {
    long n4 = sizeof(ZB) / 16;
    float4* p = (float4*)&g_zb;
    long i = (long)blockIdx.x * blockDim.x + threadIdx.x;
    if (i < n4) p[i] = make_float4(0.f, 0.f, 0.f, 0.f);
}

__global__ void k_wt(const float* __restrict__ gW, const float* __restrict__ lgW,
                     float* __restrict__ Wt) {
    int idx = blockIdx.x * blockDim.x + threadIdx.x;
    if (idx >= 6 * WT_LAYER) return;
    int layer = idx >> 13;
    int rem = idx & 8191;
    int ks = rem >> 9;
    int rem2 = rem & 511;
    int nf = rem2 >> 5, lane = rem2 & 31;
    int g = lane >> 2, tig = lane & 3;
    int n = nf * 8 + g, k = ks * 8 + tig;
    const float* W = (layer < 3) ? (gW + (long)layer * 16384)
                                 : (lgW + (long)(layer - 3) * 16384);
    Wt[(long)idx * 2 + 0] = __uint_as_float(f2tf32(__ldg(W + k * HID + n)));
    Wt[(long)idx * 2 + 1] = __uint_as_float(f2tf32(__ldg(W + (k + 4) * HID + n)));
}

__global__ void k_deg(const int* __restrict__ s, const int* __restrict__ t,
                      int* deg, int noff, int n) {
    int i = blockIdx.x * blockDim.x + threadIdx.x;
    if (i < n) {
        atomicAdd(deg + s[i], 1);
        atomicAdd(deg + noff + t[i], 1);
    }
}

__global__ void k_cnt(const int* __restrict__ seg, int* __restrict__ cnt,
                      int cntoff, int n) {
    __shared__ int h[NB];
    int t = threadIdx.x;
    if (t < NB) h[t] = 0;
    __syncthreads();
    int i = blockIdx.x * blockDim.x + t;
    if (i < n) atomicAdd(h + seg[i], 1);
    __syncthreads();
    if (t < NB && h[t]) atomicAdd(cnt + cntoff + t, h[t]);
}

__global__ void k_scan1(const int* __restrict__ deg, int* __restrict__ off,
                        int* __restrict__ bsum, int n) {
    __shared__ int sh[SCAN_BS];
    int t = threadIdx.x;
    int i = blockIdx.x * SCAN_BS + t;
    int v = (i < n) ? deg[i] : 0;
    sh[t] = v;
    __syncthreads();
    for (int s = 1; s < SCAN_BS; s <<= 1) {
        int add = (t >= s) ? sh[t - s] : 0;
        __syncthreads();
        sh[t] += add;
        __syncthreads();
    }
    if (i < n) off[i] = sh[t] - v;
    if (t == SCAN_BS - 1) bsum[blockIdx.x] = sh[t];
}
__global__ void k_scan2(int* bsum, int nb) {
    __shared__ int sh[SCAN_BS];
    int t = threadIdx.x;
    int v = (t < nb) ? bsum[t] : 0;
    sh[t] = v;
    __syncthreads();
    for (int s = 1; s < SCAN_BS; s <<= 1) {
        int add = (t >= s) ? sh[t - s] : 0;
        __syncthreads();
        sh[t] += add;
        __syncthreads();
    }
    if (t < nb) bsum[t] = sh[t] - v;
}
__global__ void k_scan3(int* __restrict__ off, const int* __restrict__ bsum,
                        int* __restrict__ cur, int n) {
    int i = blockIdx.x * blockDim.x + threadIdx.x;
    if (i < n) {
        int o = off[i] + bsum[i >> 10];
        off[i] = o;
        cur[i] = o;
    }
}
__global__ void k_fill(const int* __restrict__ s, const int* __restrict__ t,
                       int* __restrict__ cur, int* __restrict__ csr, int n) {
    int i = blockIdx.x * blockDim.x + threadIdx.x;
    if (i < n) {
        int p = atomicAdd(cur + t[i], 1);
        csr[p] = s[i];
    }
}

// ---------------- fused CSR-gather + tensor-core GEMM (device body) --------
// MODE 0: f = feat[s];  MODE 1: f = d[s]*ep_w + ep_b;  MODE 2: f = emb[z[s]]
// EPI  0: store rows;   EPI  1: red.add into pool[seg[row]*256 + coloff + n]
#define XS_STRIDE 132

struct ConvArgs {
    const float* feat;
    const int* z;
    const float* emb;
    const float* epw;
    const float* epb;
    const int* dego;
    const int* degi;
    const int* off;
    const int* csr;
    const float2* Wt;
    const float* bias;
    float* out;
    const int* seg;
    float* pool;
    int coloff;
    int rows;
};

template<int MODE, int EPI>
__device__ __forceinline__ void conv_block(int bid, const ConvArgs& a, uint32_t* Xs) {
    int tid = threadIdx.x;
    int warp = tid >> 5, lane = tid & 31;
    int g = lane >> 2, tig = lane & 3;
    long r0 = (long)bid * 64;

    // ---- phase 1: gather A-tile (warp per row) ----
    float4 wv, bv;
    if (MODE == 1) { wv = ((const float4*)a.epw)[lane]; bv = ((const float4*)a.epb)[lane]; }
    for (int rl = warp; rl < 64; rl += 4) {
        long r = r0 + rl;
        float4 acc = make_float4(0.f, 0.f, 0.f, 0.f);
        float4 acc2 = make_float4(0.f, 0.f, 0.f, 0.f);
        float si = 0.f;
        if (r < a.rows) {
            int beg = __ldg(a.off + r), dg = __ldg(a.degi + r);
            int end = beg + dg;
            int j = beg;
            if (MODE == 1) {
                for (; j < end; j++) {
                    int s = __ldg(a.csr + j);
                    float sc = rsdeg_i(__ldg(a.dego + s));
                    float dv = __ldg(a.feat + s) * sc;
                    acc.x += dv * wv.x + bv.x * sc;
                    acc.y += dv * wv.y + bv.y * sc;
                    acc.z += dv * wv.z + bv.z * sc;
                    acc.w += dv * wv.w + bv.w * sc;
                }
            } else {
                // 2-way unrolled: two independent load chains
                for (; j + 2 <= end; j += 2) {
                    int s0 = __ldg(a.csr + j);
                    int s1 = __ldg(a.csr + j + 1);
                    float sc0 = rsdeg_i(__ldg(a.dego + s0));
                    float sc1 = rsdeg_i(__ldg(a.dego + s1));
                    const float4* src0;
                    const float4* src1;
                    if (MODE == 0) {
                        src0 = (const float4*)a.feat + (long)s0 * HF4 + lane;
                        src1 = (const float4*)a.feat + (long)s1 * HF4 + lane;
                    } else {
                        src0 = (const float4*)a.emb + (long)__ldg(a.z + s0) * HF4 + lane;
                        src1 = (const float4*)a.emb + (long)__ldg(a.z + s1) * HF4 + lane;
                    }
                    float4 v0 = __ldg(src0);
                    float4 v1 = __ldg(src1);
                    acc.x  += v0.x * sc0; acc.y  += v0.y * sc0;
                    acc.z  += v0.z * sc0; acc.w  += v0.w * sc0;
                    acc2.x += v1.x * sc1; acc2.y += v1.y * sc1;
                    acc2.z += v1.z * sc1; acc2.w += v1.w * sc1;
                }
                if (j < end) {
                    int s = __ldg(a.csr + j);
                    float sc = rsdeg_i(__ldg(a.dego + s));
                    const float4* src;
                    if (MODE == 0) src = (const float4*)a.feat + (long)s * HF4 + lane;
                    else           src = (const float4*)a.emb + (long)__ldg(a.z + s) * HF4 + lane;
                    float4 v = __ldg(src);
                    acc.x += v.x * sc; acc.y += v.y * sc;
                    acc.z += v.z * sc; acc.w += v.w * sc;
                }
                acc.x += acc2.x; acc.y += acc2.y; acc.z += acc2.z; acc.w += acc2.w;
            }
            si = rsdeg_i(dg);
        }
        uint32_t* p = Xs + rl * XS_STRIDE + lane * 4;
        p[0] = f2tf32(acc.x * si); p[1] = f2tf32(acc.y * si);
        p[2] = f2tf32(acc.z * si); p[3] = f2tf32(acc.w * si);
    }
    __syncthreads();

    // ---- phase 2: 64x128 @ 128x128 tf32 MMA ----
    float acc[16][4];
#pragma unroll
    for (int nf = 0; nf < 16; nf++)
#pragma unroll
        for (int j2 = 0; j2 < 4; j2++) acc[nf][j2] = 0.f;

    const uint32_t* xa = Xs + (warp * 16 + g) * XS_STRIDE + tig;
    const uint2* wt = ((const uint2*)a.Wt) + lane;
#pragma unroll 4
    for (int ks = 0; ks < 16; ks++) {
        int k0 = ks * 8;
        uint32_t a0 = xa[k0];
        uint32_t a1 = xa[8 * XS_STRIDE + k0];
        uint32_t a2 = xa[k0 + 4];
        uint32_t a3 = xa[8 * XS_STRIDE + k0 + 4];
#pragma unroll
        for (int nf = 0; nf < 16; nf++) {
            uint2 b = __ldg(wt + (ks * 16 + nf) * 32);
            mma_tf32(acc[nf][0], acc[nf][1], acc[nf][2], acc[nf][3],
                     a0, a1, a2, a3, b.x, b.y);
        }
    }

    long row0 = r0 + warp * 16 + g;
    long row1 = row0 + 8;
    int seg0 = 0, seg1 = 0;
    if (EPI == 1) {
        if (row0 < a.rows) seg0 = __ldg(a.seg + row0);
        if (row1 < a.rows) seg1 = __ldg(a.seg + row1);
    }
#pragma unroll
    for (int nf = 0; nf < 16; nf++) {
        int n0 = nf * 8 + 2 * tig;
        float b0 = __ldg(a.bias + n0), b1 = __ldg(a.bias + n0 + 1);
        if (row0 < a.rows) {
            float ox = fmaxf(acc[nf][0] + b0, 0.f);
            float oy = fmaxf(acc[nf][1] + b1, 0.f);
            if (EPI == 0) *(float2*)(a.out + row0 * HID + n0) = make_float2(ox, oy);
            else red_add_v2(a.pool + (long)seg0 * 256 + a.coloff + n0, ox, oy);
        }
        if (row1 < a.rows) {
            float ox = fmaxf(acc[nf][2] + b0, 0.f);
            float oy = fmaxf(acc[nf][3] + b1, 0.f);
            if (EPI == 0) *(float2*)(a.out + row1 * HID + n0) = make_float2(ox, oy);
            else red_add_v2(a.pool + (long)seg1 * 256 + a.coloff + n0, ox, oy);
        }
    }
}

// combined launch: blocks [0,gA) -> graph A (line), [gA,..) -> graph B (node)
template<int MODEA, int MODEB, int EPI>
__global__ void __launch_bounds__(128)
k_conv2(ConvArgs a, ConvArgs b, int gA) {
    __shared__ __align__(16) uint32_t Xs[64 * XS_STRIDE];
    if (blockIdx.x < (unsigned)gA) conv_block<MODEA, EPI>(blockIdx.x, a, Xs);
    else                           conv_block<MODEB, EPI>(blockIdx.x - gA, b, Xs);
}

// final MLP
__global__ void k_readout(const float* __restrict__ pool, const int* __restrict__ cnt,
                          const float* __restrict__ r1w, const float* __restrict__ r1b,
                          const float* __restrict__ r2w, const float* __restrict__ r2b,
                          float* __restrict__ out) {
    __shared__ float x[256];
    __shared__ float redbuf[128];
    int g = blockIdx.x, tid = threadIdx.x;
    float cn = fmaxf((float)cnt[g], 1.f);
    float ce = fmaxf((float)cnt[NB + g], 1.f);
    x[tid]       = pool[g * 256 + tid] / cn;
    x[128 + tid] = pool[g * 256 + 128 + tid] / ce;
    __syncthreads();
    float a = r1b[tid];
#pragma unroll 8
    for (int k = 0; k < 256; k++) a += x[k] * r1w[k * 128 + tid];
    float sig = 1.f / (1.f + expf(-a));
    float p = a * sig * r2w[tid];
    redbuf[tid] = p;
    __syncthreads();
    for (int s = 64; s > 0; s >>= 1) {
        if (tid < s) redbuf[tid] += redbuf[tid + s];
        __syncthreads();
    }
    if (tid == 0) out[g] = redbuf[0] + r2b[0];
}

// ---------------- launch ----------------
static inline int cdiv(long a, long b) { return (int)((a + b - 1) / b); }

extern "C" void kernel_launch(void* const* d_in, const int* in_sizes, int n_in,
                              void* d_out, int out_size) {
    const int*   z    = (const int*)  d_in[0];
    const float* d    = (const float*)d_in[1];
    const int*   src  = (const int*)  d_in[2];
    const int*   dst  = (const int*)  d_in[3];
    const int*   lsrc = (const int*)  d_in[4];
    const int*   ldst = (const int*)  d_in[5];
    const int*   ng   = (const int*)  d_in[6];
    const int*   eg   = (const int*)  d_in[7];
    const float* emb  = (const float*)d_in[8];
    const float* epw  = (const float*)d_in[9];
    const float* epb  = (const float*)d_in[10];
    const float* gW   = (const float*)d_in[11];
    const float* gb   = (const float*)d_in[12];
    const float* lgW  = (const float*)d_in[13];
    const float* lgb  = (const float*)d_in[14];
    const float* r1w  = (const float*)d_in[15];
    const float* r1b  = (const float*)d_in[16];
    const float* r2w  = (const float*)d_in[17];
    const float* r2b  = (const float*)d_in[18];
    float* out = (float*)d_out;

    float *p_hA, *p_hB, *p_eA, *p_eB, *p_Wt;
    int *p_offN, *p_curN, *p_offE, *p_curE, *p_csrN, *p_csrE, *p_bsum;
    ZB* p_zb;
    cudaGetSymbolAddress((void**)&p_hA,   g_hA);
    cudaGetSymbolAddress((void**)&p_hB,   g_hB);
    cudaGetSymbolAddress((void**)&p_eA,   g_eA);
    cudaGetSymbolAddress((void**)&p_eB,   g_eB);
    cudaGetSymbolAddress((void**)&p_zb,   g_zb);
    cudaGetSymbolAddress((void**)&p_offN, g_offN);
    cudaGetSymbolAddress((void**)&p_curN, g_curN);
    cudaGetSymbolAddress((void**)&p_offE, g_offE);
    cudaGetSymbolAddress((void**)&p_curE, g_curE);
    cudaGetSymbolAddress((void**)&p_csrN, g_csrN);
    cudaGetSymbolAddress((void**)&p_csrE, g_csrE);
    cudaGetSymbolAddress((void**)&p_bsum, g_bsum);
    cudaGetSymbolAddress((void**)&p_Wt,   g_Wt);

    int* p_degNo = p_zb->degN;
    int* p_degNi = p_zb->degN + NNODES;
    int* p_degEo = p_zb->degE;
    int* p_degEi = p_zb->degE + NEDGES;
    int* p_cnt   = p_zb->cnt;
    float* p_pool = p_zb->pool;

    const float2* wtL[6];
    for (int l = 0; l < 6; l++) wtL[l] = (const float2*)p_Wt + (long)l * WT_LAYER;

    const int T = 256;

    k_zero_all<<<cdiv(sizeof(ZB) / 16, T), T>>>();
    k_wt<<<cdiv(6 * WT_LAYER, T), T>>>(gW, lgW, p_Wt);
    k_cnt<<<cdiv(NNODES, T), T>>>(ng, p_cnt, 0, NNODES);
    k_cnt<<<cdiv(NEDGES, T), T>>>(eg, p_cnt, NB, NEDGES);

    // ---- CSR build: line graph ----
    k_deg<<<cdiv(NEDGES2, T), T>>>(lsrc, ldst, p_degEo, NEDGES, NEDGES2);
    k_scan1<<<cdiv(NEDGES, SCAN_BS), SCAN_BS>>>(p_degEi, p_offE, p_bsum, NEDGES);
    k_scan2<<<1, SCAN_BS>>>(p_bsum, cdiv(NEDGES, SCAN_BS));
    k_scan3<<<cdiv(NEDGES, T), T>>>(p_offE, p_bsum, p_curE, NEDGES);
    k_fill<<<cdiv(NEDGES2, T), T>>>(lsrc, ldst, p_curE, p_csrE, NEDGES2);
    // ---- CSR build: node graph ----
    k_deg<<<cdiv(NEDGES, T), T>>>(src, dst, p_degNo, NNODES, NEDGES);
    k_scan1<<<cdiv(NNODES, SCAN_BS), SCAN_BS>>>(p_degNi, p_offN, p_bsum, NNODES);
    k_scan2<<<1, SCAN_BS>>>(p_bsum, cdiv(NNODES, SCAN_BS));
    k_scan3<<<cdiv(NNODES, T), T>>>(p_offN, p_bsum, p_curN, NNODES);
    k_fill<<<cdiv(NEDGES, T), T>>>(src, dst, p_curN, p_csrN, NEDGES);

    const int gE = cdiv(NEDGES, 64), gN = cdiv(NNODES, 64);

    // common arg skeletons
    ConvArgs la = {};
    la.dego = p_degEo; la.degi = p_degEi; la.off = p_offE; la.csr = p_csrE;
    la.rows = NEDGES;  la.seg = eg;  la.pool = p_pool; la.coloff = 128;
    ConvArgs na = {};
    na.dego = p_degNo; na.degi = p_degNi; na.off = p_offN; na.csr = p_csrN;
    na.rows = NNODES;  na.seg = ng;  na.pool = p_pool; na.coloff = 0;

    // ---- layer 1: line(MODE1) + node(MODE2) combined ----
    {
        ConvArgs A = la; A.feat = d; A.epw = epw; A.epb = epb;
        A.Wt = wtL[3]; A.bias = lgb; A.out = p_eA;
        ConvArgs B = na; B.z = z; B.emb = emb;
        B.Wt = wtL[0]; B.bias = gb; B.out = p_hA;
        k_conv2<1, 2, 0><<<gE + gN, 128>>>(A, B, gE);
    }
    // ---- layer 2: both MODE0 ----
    {
        ConvArgs A = la; A.feat = p_eA; A.Wt = wtL[4]; A.bias = lgb + HID; A.out = p_eB;
        ConvArgs B = na; B.feat = p_hA; B.Wt = wtL[1]; B.bias = gb + HID;  B.out = p_hB;
        k_conv2<0, 0, 0><<<gE + gN, 128>>>(A, B, gE);
    }
    // ---- layer 3: both MODE0, pooling epilogue ----
    {
        ConvArgs A = la; A.feat = p_eB; A.Wt = wtL[5]; A.bias = lgb + 2 * HID;
        ConvArgs B = na; B.feat = p_hB; B.Wt = wtL[2]; B.bias = gb + 2 * HID;
        k_conv2<0, 0, 1><<<gE + gN, 128>>>(A, B, gE);
    }

    // ---- readout ----
    k_readout<<<NB, 128>>>(p_pool, p_cnt, r1w, r1b, r2w, r2b, out);
}